// round 15
// baseline (speedup 1.0000x reference)
#include <cuda_runtime.h>
#include <cuda_fp16.h>
#include <math.h>
#include <stdint.h>

// ---------------- problem constants ----------------
#define NL    6
#define DMODEL 768
#define NH    12
#define DFF_  3072
#define BB    8
#define TLEN_ 512
#define SLEN_ 512
#define DH_   64
#define BT_   (BB*TLEN_)   // 4096 target tokens
#define BS_   (BB*SLEN_)   // 4096 source tokens

// ---------------- scratch (device globals: allocation-free) ----------------
__device__ float  g_res [BT_*DMODEL];
__device__ float  g_res2[BT_*DMODEL];
__device__ __half g_lnb [BT_*DMODEL];
__device__ __half g_qkv [BT_*3*DMODEL];
__device__ __half g_kv  [BS_*2*DMODEL];
__device__ __half g_ctx [BT_*DMODEL];
__device__ __half g_ff  [BT_*DFF_];
// fp16 pre-converted weights / memory
__device__ __half g_wsa[(size_t)NL*4*DMODEL*DMODEL];
__device__ __half g_wca[(size_t)NL*4*DMODEL*DMODEL];
__device__ __half g_w1 [(size_t)NL*DFF_*DMODEL];
__device__ __half g_w2 [(size_t)NL*DMODEL*DFF_];
__device__ __half g_mem[(size_t)BS_*DMODEL];

// ---------------- fp16 mma helper ----------------
__device__ __forceinline__ void mma_f16(float c[4], const uint32_t a[4], const uint32_t b[2])
{
    asm volatile(
        "mma.sync.aligned.m16n8k16.row.col.f32.f16.f16.f32 "
        "{%0,%1,%2,%3}, {%4,%5,%6,%7}, {%8,%9}, {%0,%1,%2,%3};"
        : "+f"(c[0]), "+f"(c[1]), "+f"(c[2]), "+f"(c[3])
        : "r"(a[0]), "r"(a[1]), "r"(a[2]), "r"(a[3]), "r"(b[0]), "r"(b[1]));
}

// ldmatrix x4: 4x 8x8 b16 matrices; lane i supplies row address for matrix i>>3
__device__ __forceinline__ void ldsm_x4(uint32_t r[4], uint32_t saddr)
{
    asm volatile(
        "ldmatrix.sync.aligned.m8n8.x4.shared.b16 {%0,%1,%2,%3}, [%4];"
        : "=r"(r[0]), "=r"(r[1]), "=r"(r[2]), "=r"(r[3]) : "r"(saddr));
}

__device__ __forceinline__ void cp16h(__half* dst, const __half* src)
{
    uint32_t s = (uint32_t)__cvta_generic_to_shared(dst);
    asm volatile("cp.async.cg.shared.global [%0], [%1], 16;" :: "r"(s), "l"(src));
}

__device__ __forceinline__ uint32_t ldsm_u32(const __half* p)
{
    return *(const uint32_t*)p;
}

// ---------------- fused fp16 pre-convert kernel ----------------
__global__ void conv_all_kernel(const float4* __restrict__ sa, const float4* __restrict__ ca,
                                const float4* __restrict__ f1, const float4* __restrict__ f2,
                                const float4* __restrict__ mm,
                                __half* __restrict__ osa, __half* __restrict__ oca,
                                __half* __restrict__ of1, __half* __restrict__ of2,
                                __half* __restrict__ omm)
{
    const size_t NW = (size_t)NL*4*DMODEL*DMODEL/4;
    const size_t NF = (size_t)NL*DFF_*DMODEL/4;
    const size_t NM = (size_t)BS_*DMODEL/4;
    size_t i = (size_t)blockIdx.x*256 + threadIdx.x;
    const float4* src; __half* dst; size_t off;
    if      (i < NW)               { src = sa; dst = osa; off = i; }
    else if (i < 2*NW)             { src = ca; dst = oca; off = i - NW; }
    else if (i < 2*NW + NF)        { src = f1; dst = of1; off = i - 2*NW; }
    else if (i < 2*NW + 2*NF)      { src = f2; dst = of2; off = i - 2*NW - NF; }
    else if (i < 2*NW + 2*NF + NM) { src = mm; dst = omm; off = i - 2*NW - 2*NF; }
    else return;
    float4 v = src[off];
    __half2 h01 = __floats2half2_rn(v.x, v.y);
    __half2 h23 = __floats2half2_rn(v.z, v.w);
    uint2 st;
    st.x = *(uint32_t*)&h01;
    st.y = *(uint32_t*)&h23;
    *(uint2*)(dst + off*4) = st;
}

// ---------------- embedding + positional encoding ----------------
__global__ void embed_kernel(const int* __restrict__ tgt,
                             const float* __restrict__ emb,
                             float* __restrict__ out)
{
    int row = blockIdx.x;
    int t   = row & (TLEN_ - 1);
    int tok = tgt[row];
    const float* e = emb + (size_t)tok * DMODEL;
    const float c = (float)(-9.210340371976184 / (double)DMODEL);
    for (int d = threadIdx.x; d < DMODEL; d += blockDim.x) {
        int k2 = d & ~1;
        float div = expf((float)k2 * c);
        float ang = (float)t * div;
        float pe  = (d & 1) ? cosf(ang) : sinf(ang);
        out[(size_t)row*DMODEL + d] = e[d] * 27.712812921102035f + pe;
    }
}

// ---------------- layernorm ----------------
__device__ __forceinline__ float blockReduceSum(float v)
{
    __shared__ float sh[9];
    int lane = threadIdx.x & 31, w = threadIdx.x >> 5;
    #pragma unroll
    for (int o = 16; o; o >>= 1) v += __shfl_xor_sync(0xffffffffu, v, o);
    __syncthreads();
    if (lane == 0) sh[w] = v;
    __syncthreads();
    if (threadIdx.x == 0) {
        float t = 0.f;
        #pragma unroll
        for (int i = 0; i < 8; i++) t += sh[i];
        sh[8] = t;
    }
    __syncthreads();
    return sh[8];
}

template<bool OUTH>
__global__ __launch_bounds__(256) void ln_kernel(const float* __restrict__ X,
                                                 const float* __restrict__ gam,
                                                 const float* __restrict__ bet,
                                                 void* __restrict__ Yv)
{
    int row = blockIdx.x;
    const float* x = X + (size_t)row * DMODEL;
    float s = 0.f;
    for (int d = threadIdx.x; d < DMODEL; d += 256) s += x[d];
    s = blockReduceSum(s);
    float mean = s / (float)DMODEL;
    float v = 0.f;
    for (int d = threadIdx.x; d < DMODEL; d += 256) { float t = x[d] - mean; v += t * t; }
    v = blockReduceSum(v);
    float inv = rsqrtf(v / (float)DMODEL + 1e-6f);
    for (int d = threadIdx.x; d < DMODEL; d += 256) {
        float y = (x[d] - mean) * inv * gam[d] + bet[d];
        if (OUTH) ((__half*)Yv)[(size_t)row*DMODEL + d] = __float2half_rn(y);
        else      ((float*)Yv)[(size_t)row*DMODEL + d] = y;
    }
}

// ---------------- fp16 tensor-core GEMM (512 thr, 4-stage cp.async + ldmatrix)
// C[M,N] = A[M,K] @ W[N,K]^T (+bias)(+gelu)(+resid), A/W fp16, acc fp32.
// 128x128 block tile, BK=32 halves, 512 threads = 16 warps (4x4), warp 32x32.
// Fragments via ldmatrix.x4: row stride 40 halves (80B) conflict-free.
// 4-stage pipeline (wait_group 2). 2 CTAs/SM -> 32 warps/SM.

#define HST 40
#define HTILE (128*HST)          // halves per tile (5120)
#define HSTAGE (2*HTILE)         // A+B halves per stage
#define GEMM_SMEM (4*HSTAGE*2)   // 81920 bytes -> 2 CTAs/SM

template<bool BIAS, bool RESID, bool GELU, bool OUTH>
__global__ __launch_bounds__(512, 2) void gemm_h(
    const __half* __restrict__ A, const __half* __restrict__ W,
    const float* __restrict__ bias, const float* __restrict__ Rm,
    void* __restrict__ Cv, int M, int N, int K)
{
    extern __shared__ __half sh[];
    const uint32_t sbase = (uint32_t)__cvta_generic_to_shared(sh);

    const int tid  = threadIdx.x;
    const int warp = tid >> 5, lane = tid & 31;
    const int gid  = lane >> 2, tig = lane & 3;
    const int brow = blockIdx.y * 128, bcol = blockIdx.x * 128;
    const int wr   = (warp >> 2) * 32;   // warp row offset (0,32,64,96)
    const int wc   = (warp & 3) * 32;    // warp col offset (0,32,64,96)

    // per-lane ldmatrix address components (matrix index = lane>>3)
    const int subm   = lane >> 3;
    const int l8     = lane & 7;
    const int a_row  = wr + ((subm & 1) << 3) + l8;   // + mt*16
    const int a_koff = (subm >> 1) << 3;              // + kb
    const int b_row  = wc + ((subm >> 1) << 3) + l8;  // + ntp*16
    const int b_koff = (subm & 1) << 3;               // + kb

    const __half* Abase = A + (size_t)brow * K;
    const __half* Wbase = W + (size_t)bcol * K;

    float acc[2][4][4];
    #pragma unroll
    for (int mt = 0; mt < 2; mt++)
        #pragma unroll
        for (int nt = 0; nt < 4; nt++)
            #pragma unroll
            for (int r = 0; r < 4; r++) acc[mt][nt][r] = 0.f;

    const int niter = K >> 5;    // BK = 32 halves

    // stage loader: tile = 128 rows x 32 halves = 512 16B-chunks; 1/thread/tile
    auto load_stage = [&](int it, int s) {
        __half* as = sh + s*HSTAGE;
        __half* bs = as + HTILE;
        int r = tid >> 2, cc = tid & 3;
        cp16h(as + r*HST + cc*8, Abase + (size_t)r*K + it*32 + cc*8);
        cp16h(bs + r*HST + cc*8, Wbase + (size_t)r*K + it*32 + cc*8);
        asm volatile("cp.async.commit_group;");
    };

    load_stage(0, 0);
    load_stage(1, 1);
    load_stage(2, 2);

    for (int it = 0; it < niter; it++) {
        if      (it + 3 <= niter) asm volatile("cp.async.wait_group 2;");
        else if (it + 2 == niter) asm volatile("cp.async.wait_group 1;");
        else                      asm volatile("cp.async.wait_group 0;");
        __syncthreads();

        if (it + 3 < niter) load_stage(it + 3, (it + 3) & 3);

        const uint32_t as_u = sbase + (uint32_t)((it & 3)*HSTAGE)*2;
        const uint32_t bs_u = as_u + HTILE*2;

        #pragma unroll
        for (int ksx = 0; ksx < 2; ksx++) {       // 2 x K=16 per chunk
            const int kb = ksx * 16;
            uint32_t afr[2][4];
            #pragma unroll
            for (int mt = 0; mt < 2; mt++)
                ldsm_x4(afr[mt], as_u + (uint32_t)((a_row + mt*16)*HST + kb + a_koff)*2);
            #pragma unroll
            for (int ntp = 0; ntp < 2; ntp++) {
                uint32_t bfr[4];
                ldsm_x4(bfr, bs_u + (uint32_t)((b_row + ntp*16)*HST + kb + b_koff)*2);
                mma_f16(acc[0][2*ntp    ], afr[0], bfr    );
                mma_f16(acc[1][2*ntp    ], afr[1], bfr    );
                mma_f16(acc[0][2*ntp + 1], afr[0], bfr + 2);
                mma_f16(acc[1][2*ntp + 1], afr[1], bfr + 2);
            }
        }
    }

    #pragma unroll
    for (int mt = 0; mt < 2; mt++) {
        #pragma unroll
        for (int half = 0; half < 2; half++) {
            int row = brow + wr + mt*16 + gid + half*8;
            #pragma unroll
            for (int nt = 0; nt < 4; nt++) {
                int col = bcol + wc + nt*8 + 2*tig;
                float v0 = acc[mt][nt][half*2 + 0];
                float v1 = acc[mt][nt][half*2 + 1];
                if (BIAS) { v0 += bias[col]; v1 += bias[col+1]; }
                if (GELU) {
                    float u0 = v0, u1 = v1;
                    v0 = 0.5f*u0*(1.f + tanhf(0.7978845608028654f*(u0 + 0.044715f*u0*u0*u0)));
                    v1 = 0.5f*u1*(1.f + tanhf(0.7978845608028654f*(u1 + 0.044715f*u1*u1*u1)));
                }
                if (RESID) {
                    v0 += Rm[(size_t)row*N + col];
                    v1 += Rm[(size_t)row*N + col + 1];
                }
                if (OUTH) {
                    __half2 hv = __floats2half2_rn(v0, v1);
                    *(__half2*)&((__half*)Cv)[(size_t)row*N + col] = hv;
                } else {
                    *(float2*)&((float*)Cv)[(size_t)row*N + col] = make_float2(v0, v1);
                }
            }
        }
    }
}

// ---------------- fp16 tensor-core flash attention (R12-proven) ----------------
#define AQST 72
#define VST2 36
#define ATTN_SMEM (2*64*AQST*2 + 64*VST2*4)   // 27648 bytes

template<bool CAUSAL>
__global__ __launch_bounds__(128) void attn_h(
    const __half* __restrict__ Q, int qstride,
    const __half* __restrict__ Kp, int kstride,
    const __half* __restrict__ Vp, int vstride,
    const int*  __restrict__ tok, int klen,
    __half* __restrict__ O, int ostride)
{
    extern __shared__ char smraw[];
    __half*   qs   = (__half*)smraw;                       // [64][72]
    __half*   ks   = qs + 64*AQST;                          // [64][72], reused for P
    uint32_t* vst2 = (uint32_t*)(smraw + 2*64*AQST*2);      // [64][36]
    __shared__ int smask[64];

    const int tid  = threadIdx.x;
    const int warp = tid >> 5, lane = tid & 31;
    const int gid  = lane >> 2, tig = lane & 3;
    const int wrow = warp * 16;
    const int qt = blockIdx.x, h = blockIdx.y, b = blockIdx.z;
    const int qbase = qt * 64;

    {
        int lr = tid >> 1;
        int lc = (tid & 1) * 32;
        const __half* qp = Q + (size_t)(b*TLEN_ + qbase + lr)*qstride + h*DH_ + lc;
        const __half2 sc = __float2half2_rn(0.125f);
        #pragma unroll
        for (int j = 0; j < 4; j++) {
            uint4 raw = *(const uint4*)(qp + j*8);
            __half2* hv = (__half2*)&raw;
            hv[0] = __hmul2(hv[0], sc); hv[1] = __hmul2(hv[1], sc);
            hv[2] = __hmul2(hv[2], sc); hv[3] = __hmul2(hv[3], sc);
            *(uint4*)(qs + lr*AQST + lc + j*8) = raw;
        }
    }

    float m[2] = {-INFINITY, -INFINITY};
    float l[2] = {0.f, 0.f};
    float oacc[8][4];
    #pragma unroll
    for (int nt = 0; nt < 8; nt++)
        #pragma unroll
        for (int r = 0; r < 4; r++) oacc[nt][r] = 0.f;

    const int nkt = CAUSAL ? (qt + 1) : (klen >> 6);
    for (int kt = 0; kt < nkt; kt++) {
        __syncthreads();

        {
            int lr = tid >> 1;
            int lc = (tid & 1) * 32;
            const __half* kp = Kp + (size_t)(b*klen + kt*64 + lr)*kstride + h*DH_ + lc;
            #pragma unroll
            for (int j = 0; j < 4; j++)
                *(uint4*)(ks + lr*AQST + lc + j*8) = *(const uint4*)(kp + j*8);
            if (tid < 64) smask[tid] = (tok[b*klen + kt*64 + tid] == 0);
        }

        {
            int vr = tid & 31;
            int vh = (tid >> 5) & 1;
            int vg = tid >> 6;
            int dbase = vh*32 + vg*16;
            const __half* v0p = Vp + (size_t)(b*klen + kt*64 + 2*vr)*vstride + h*DH_ + dbase;
            const __half* v1p = v0p + vstride;
            __half va[16], vb[16];
            *(uint4*)&va[0] = *(const uint4*)v0p;
            *(uint4*)&va[8] = *(const uint4*)(v0p + 8);
            *(uint4*)&vb[0] = *(const uint4*)v1p;
            *(uint4*)&vb[8] = *(const uint4*)(v1p + 8);
            #pragma unroll
            for (int j = 0; j < 16; j++) {
                __half2 p = __halves2half2(va[j], vb[j]);
                vst2[(dbase + j)*VST2 + vr] = *(uint32_t*)&p;
            }
        }
        __syncthreads();

        float sfr[8][4];
        #pragma unroll
        for (int nt = 0; nt < 8; nt++)
            #pragma unroll
            for (int r = 0; r < 4; r++) sfr[nt][r] = 0.f;

        #pragma unroll
        for (int ks16 = 0; ks16 < 4; ks16++) {
            const int kb = ks16*16;
            uint32_t a[4];
            a[0] = ldsm_u32(&qs[(wrow+gid  )*AQST + kb + 2*tig    ]);
            a[1] = ldsm_u32(&qs[(wrow+gid+8)*AQST + kb + 2*tig    ]);
            a[2] = ldsm_u32(&qs[(wrow+gid  )*AQST + kb + 2*tig + 8]);
            a[3] = ldsm_u32(&qs[(wrow+gid+8)*AQST + kb + 2*tig + 8]);
            #pragma unroll
            for (int nt = 0; nt < 8; nt++) {
                uint32_t bf[2];
                bf[0] = ldsm_u32(&ks[(nt*8+gid)*AQST + kb + 2*tig    ]);
                bf[1] = ldsm_u32(&ks[(nt*8+gid)*AQST + kb + 2*tig + 8]);
                mma_f16(sfr[nt], a, bf);
            }
        }

        #pragma unroll
        for (int nt = 0; nt < 8; nt++) {
            #pragma unroll
            for (int e = 0; e < 4; e++) {
                int cl = nt*8 + 2*tig + (e & 1);
                int rowg = qbase + wrow + gid + (e >> 1)*8;
                int colg = kt*64 + cl;
                bool msk = (smask[cl] != 0) || (CAUSAL && colg > rowg);
                if (msk) sfr[nt][e] = -1e18f;
            }
        }

        #pragma unroll
        for (int h2 = 0; h2 < 2; h2++) {
            float rm = -INFINITY;
            #pragma unroll
            for (int nt = 0; nt < 8; nt++)
                rm = fmaxf(rm, fmaxf(sfr[nt][h2*2], sfr[nt][h2*2+1]));
            rm = fmaxf(rm, __shfl_xor_sync(0xffffffffu, rm, 1));
            rm = fmaxf(rm, __shfl_xor_sync(0xffffffffu, rm, 2));
            float nm = fmaxf(m[h2], rm);
            float alpha = __expf(m[h2] - nm);
            float rs = 0.f;
            #pragma unroll
            for (int nt = 0; nt < 8; nt++) {
                float p0 = __expf(sfr[nt][h2*2]   - nm);
                float p1 = __expf(sfr[nt][h2*2+1] - nm);
                sfr[nt][h2*2] = p0; sfr[nt][h2*2+1] = p1;
                rs += p0 + p1;
            }
            rs += __shfl_xor_sync(0xffffffffu, rs, 1);
            rs += __shfl_xor_sync(0xffffffffu, rs, 2);
            l[h2] = l[h2]*alpha + rs;
            m[h2] = nm;
            #pragma unroll
            for (int nt = 0; nt < 8; nt++) {
                oacc[nt][h2*2]   *= alpha;
                oacc[nt][h2*2+1] *= alpha;
            }
        }

        __syncthreads();

        #pragma unroll
        for (int nt = 0; nt < 8; nt++) {
            #pragma unroll
            for (int h2 = 0; h2 < 2; h2++) {
                __half2 hp = __floats2half2_rn(sfr[nt][h2*2], sfr[nt][h2*2+1]);
                *(__half2*)&ks[(wrow + gid + h2*8)*AQST + nt*8 + 2*tig] = hp;
            }
        }
        __syncwarp();

        #pragma unroll
        for (int ks16 = 0; ks16 < 4; ks16++) {
            const int kb  = ks16*16;
            const int kb2 = ks16*8;
            uint32_t a[4];
            a[0] = ldsm_u32(&ks[(wrow+gid  )*AQST + kb + 2*tig    ]);
            a[1] = ldsm_u32(&ks[(wrow+gid+8)*AQST + kb + 2*tig    ]);
            a[2] = ldsm_u32(&ks[(wrow+gid  )*AQST + kb + 2*tig + 8]);
            a[3] = ldsm_u32(&ks[(wrow+gid+8)*AQST + kb + 2*tig + 8]);
            #pragma unroll
            for (int nt = 0; nt < 8; nt++) {
                uint32_t bf[2];
                bf[0] = vst2[(nt*8+gid)*VST2 + kb2 + tig    ];
                bf[1] = vst2[(nt*8+gid)*VST2 + kb2 + tig + 4];
                mma_f16(oacc[nt], a, bf);
            }
        }
    }

    float inv0 = 1.f / l[0];
    float inv1 = 1.f / l[1];
    size_t r0 = (size_t)(b*TLEN_ + qbase + wrow + gid)*ostride + h*DH_;
    size_t r1 = r0 + (size_t)8*ostride;
    #pragma unroll
    for (int nt = 0; nt < 8; nt++) {
        int col = nt*8 + 2*tig;
        __half2 o0 = __floats2half2_rn(oacc[nt][0]*inv0, oacc[nt][1]*inv0);
        __half2 o1 = __floats2half2_rn(oacc[nt][2]*inv1, oacc[nt][3]*inv1);
        *(__half2*)&O[r0 + col] = o0;
        *(__half2*)&O[r1 + col] = o1;
    }
}

// ---------------- host orchestration ----------------
extern "C" void kernel_launch(void* const* d_in, const int* in_sizes, int n_in,
                              void* d_out, int out_size)
{
    (void)in_sizes; (void)n_in; (void)out_size;
    const int*   tgt    = (const int*)  d_in[0];
    const int*   src    = (const int*)  d_in[1];
    const float* memory = (const float*)d_in[2];
    const float* emb    = (const float*)d_in[3];
    const float* sa_w   = (const float*)d_in[4];
    const float* sa_b   = (const float*)d_in[5];
    const float* ca_w   = (const float*)d_in[6];
    const float* ca_b   = (const float*)d_in[7];
    const float* ln_g   = (const float*)d_in[8];
    const float* ln_b   = (const float*)d_in[9];
    const float* ff_w1  = (const float*)d_in[10];
    const float* ff_b1  = (const float*)d_in[11];
    const float* ff_w2  = (const float*)d_in[12];
    const float* ff_b2  = (const float*)d_in[13];
    const float* out_g  = (const float*)d_in[14];
    const float* out_b  = (const float*)d_in[15];
    float* out = (float*)d_out;

    float *res, *res2;
    __half *lnb, *qkv, *kv, *ctx, *ff, *wsa, *wca, *w1, *w2, *mem;
    cudaGetSymbolAddress((void**)&res,  g_res);
    cudaGetSymbolAddress((void**)&res2, g_res2);
    cudaGetSymbolAddress((void**)&lnb,  g_lnb);
    cudaGetSymbolAddress((void**)&qkv,  g_qkv);
    cudaGetSymbolAddress((void**)&kv,   g_kv);
    cudaGetSymbolAddress((void**)&ctx,  g_ctx);
    cudaGetSymbolAddress((void**)&ff,   g_ff);
    cudaGetSymbolAddress((void**)&wsa,  g_wsa);
    cudaGetSymbolAddress((void**)&wca,  g_wca);
    cudaGetSymbolAddress((void**)&w1,   g_w1);
    cudaGetSymbolAddress((void**)&w2,   g_w2);
    cudaGetSymbolAddress((void**)&mem,  g_mem);

    cudaFuncSetAttribute(attn_h<true>,  cudaFuncAttributeMaxDynamicSharedMemorySize, ATTN_SMEM);
    cudaFuncSetAttribute(attn_h<false>, cudaFuncAttributeMaxDynamicSharedMemorySize, ATTN_SMEM);
    cudaFuncSetAttribute((gemm_h<true,false,false,true >), cudaFuncAttributeMaxDynamicSharedMemorySize, GEMM_SMEM);
    cudaFuncSetAttribute((gemm_h<true,true ,false,false>), cudaFuncAttributeMaxDynamicSharedMemorySize, GEMM_SMEM);
    cudaFuncSetAttribute((gemm_h<true,false,true ,true >), cudaFuncAttributeMaxDynamicSharedMemorySize, GEMM_SMEM);

    embed_kernel<<<BT_, 256>>>(tgt, emb, res);
    {
        const size_t NW = (size_t)NL*4*DMODEL*DMODEL/4;
        const size_t NF = (size_t)NL*DFF_*DMODEL/4;
        const size_t NM = (size_t)BS_*DMODEL/4;
        const size_t total = 2*NW + 2*NF + NM;
        conv_all_kernel<<<(unsigned)((total + 255)/256), 256>>>(
            (const float4*)sa_w, (const float4*)ca_w,
            (const float4*)ff_w1, (const float4*)ff_w2, (const float4*)memory,
            wsa, wca, w1, w2, mem);
    }

    const dim3 g768 (DMODEL/128, BT_/128);
    const dim3 g1536(2*DMODEL/128, BS_/128);
    const dim3 g2304(3*DMODEL/128, BT_/128);
    const dim3 g3072(DFF_/128, BT_/128);
    const dim3 attn_grid(TLEN_/64, NH, BB);

    for (int i = 0; i < NL; i++) {
        const __half* saw = wsa + (size_t)i*4*DMODEL*DMODEL;
        const float*  sab = sa_b + (size_t)i*4*DMODEL;
        const __half* caw = wca + (size_t)i*4*DMODEL*DMODEL;
        const float*  cab = ca_b + (size_t)i*4*DMODEL;
        const float*  lg  = ln_g + (size_t)i*3*DMODEL;
        const float*  lb  = ln_b + (size_t)i*3*DMODEL;

        // ----- self attention -----
        ln_kernel<true><<<BT_, 256>>>(res, lg, lb, lnb);
        gemm_h<true,false,false,true><<<g2304, 512, GEMM_SMEM>>>(lnb, saw, sab, nullptr, qkv,
                                                  BT_, 3*DMODEL, DMODEL);
        attn_h<true><<<attn_grid, 128, ATTN_SMEM>>>(
            qkv, 3*DMODEL, qkv + DMODEL, 3*DMODEL, qkv + 2*DMODEL, 3*DMODEL,
            tgt, TLEN_, ctx, DMODEL);
        gemm_h<true,true,false,false><<<g768, 512, GEMM_SMEM>>>(ctx, saw + (size_t)3*DMODEL*DMODEL,
                                                sab + 3*DMODEL, res, res2,
                                                BT_, DMODEL, DMODEL);

        // ----- cross attention -----
        ln_kernel<true><<<BT_, 256>>>(res2, lg + DMODEL, lb + DMODEL, lnb);
        gemm_h<true,false,false,true><<<g768, 512, GEMM_SMEM>>>(lnb, caw, cab, nullptr, qkv,
                                                 BT_, DMODEL, DMODEL);
        gemm_h<true,false,false,true><<<g1536, 512, GEMM_SMEM>>>(mem, caw + (size_t)DMODEL*DMODEL,
                                                  cab + DMODEL, nullptr, kv,
                                                  BS_, 2*DMODEL, DMODEL);
        attn_h<false><<<attn_grid, 128, ATTN_SMEM>>>(
            qkv, DMODEL, kv, 2*DMODEL, kv + DMODEL, 2*DMODEL,
            src, SLEN_, ctx, DMODEL);
        gemm_h<true,true,false,false><<<g768, 512, GEMM_SMEM>>>(ctx, caw + (size_t)3*DMODEL*DMODEL,
                                                cab + 3*DMODEL, res2, res,
                                                BT_, DMODEL, DMODEL);

        // ----- FFN -----
        ln_kernel<true><<<BT_, 256>>>(res, lg + 2*DMODEL, lb + 2*DMODEL, lnb);
        gemm_h<true,false,true,true><<<g3072, 512, GEMM_SMEM>>>(lnb, w1 + (size_t)i*DFF_*DMODEL,
                                                 ff_b1 + (size_t)i*DFF_, nullptr, ff,
                                                 BT_, DFF_, DMODEL);
        gemm_h<true,true,false,false><<<g768, 512, GEMM_SMEM>>>(ff, w2 + (size_t)i*DMODEL*DFF_,
                                                ff_b2 + (size_t)i*DMODEL, res, res2,
                                                BT_, DMODEL, DFF_);

        float* tmp = res; res = res2; res2 = tmp;
    }

    ln_kernel<false><<<BT_, 256>>>(res, out_g, out_b, out);
}

// round 16
// speedup vs baseline: 1.1059x; 1.1059x over previous
#include <cuda_runtime.h>
#include <cuda_fp16.h>
#include <math.h>
#include <stdint.h>

// ---------------- problem constants ----------------
#define NL    6
#define DMODEL 768
#define NH    12
#define DFF_  3072
#define BB    8
#define TLEN_ 512
#define SLEN_ 512
#define DH_   64
#define BT_   (BB*TLEN_)   // 4096 target tokens
#define BS_   (BB*SLEN_)   // 4096 source tokens

// ---------------- scratch (device globals: allocation-free) ----------------
__device__ float  g_res [BT_*DMODEL];
__device__ float  g_res2[BT_*DMODEL];
__device__ __half g_lnb [BT_*DMODEL];
__device__ __half g_qkv [BT_*3*DMODEL];
__device__ __half g_kv  [BS_*2*DMODEL];
__device__ __half g_ctx [BT_*DMODEL];
__device__ __half g_ff  [BT_*DFF_];
// fp16 pre-converted weights / memory
__device__ __half g_wsa[(size_t)NL*4*DMODEL*DMODEL];
__device__ __half g_wca[(size_t)NL*4*DMODEL*DMODEL];
__device__ __half g_w1 [(size_t)NL*DFF_*DMODEL];
__device__ __half g_w2 [(size_t)NL*DMODEL*DFF_];
__device__ __half g_mem[(size_t)BS_*DMODEL];

// ---------------- fp16 mma helper ----------------
__device__ __forceinline__ void mma_f16(float c[4], const uint32_t a[4], const uint32_t b[2])
{
    asm volatile(
        "mma.sync.aligned.m16n8k16.row.col.f32.f16.f16.f32 "
        "{%0,%1,%2,%3}, {%4,%5,%6,%7}, {%8,%9}, {%0,%1,%2,%3};"
        : "+f"(c[0]), "+f"(c[1]), "+f"(c[2]), "+f"(c[3])
        : "r"(a[0]), "r"(a[1]), "r"(a[2]), "r"(a[3]), "r"(b[0]), "r"(b[1]));
}

// ldmatrix x4: 4x 8x8 b16 matrices; lane i supplies row address for matrix i>>3
__device__ __forceinline__ void ldsm_x4(uint32_t r[4], uint32_t saddr)
{
    asm volatile(
        "ldmatrix.sync.aligned.m8n8.x4.shared.b16 {%0,%1,%2,%3}, [%4];"
        : "=r"(r[0]), "=r"(r[1]), "=r"(r[2]), "=r"(r[3]) : "r"(saddr));
}

__device__ __forceinline__ void cp16h(__half* dst, const __half* src)
{
    uint32_t s = (uint32_t)__cvta_generic_to_shared(dst);
    asm volatile("cp.async.cg.shared.global [%0], [%1], 16;" :: "r"(s), "l"(src));
}

__device__ __forceinline__ uint32_t ldsm_u32(const __half* p)
{
    return *(const uint32_t*)p;
}

// ---------------- fused fp16 pre-convert kernel ----------------
__global__ void conv_all_kernel(const float4* __restrict__ sa, const float4* __restrict__ ca,
                                const float4* __restrict__ f1, const float4* __restrict__ f2,
                                const float4* __restrict__ mm,
                                __half* __restrict__ osa, __half* __restrict__ oca,
                                __half* __restrict__ of1, __half* __restrict__ of2,
                                __half* __restrict__ omm)
{
    const size_t NW = (size_t)NL*4*DMODEL*DMODEL/4;
    const size_t NF = (size_t)NL*DFF_*DMODEL/4;
    const size_t NM = (size_t)BS_*DMODEL/4;
    size_t i = (size_t)blockIdx.x*256 + threadIdx.x;
    const float4* src; __half* dst; size_t off;
    if      (i < NW)               { src = sa; dst = osa; off = i; }
    else if (i < 2*NW)             { src = ca; dst = oca; off = i - NW; }
    else if (i < 2*NW + NF)        { src = f1; dst = of1; off = i - 2*NW; }
    else if (i < 2*NW + 2*NF)      { src = f2; dst = of2; off = i - 2*NW - NF; }
    else if (i < 2*NW + 2*NF + NM) { src = mm; dst = omm; off = i - 2*NW - 2*NF; }
    else return;
    float4 v = src[off];
    __half2 h01 = __floats2half2_rn(v.x, v.y);
    __half2 h23 = __floats2half2_rn(v.z, v.w);
    uint2 st;
    st.x = *(uint32_t*)&h01;
    st.y = *(uint32_t*)&h23;
    *(uint2*)(dst + off*4) = st;
}

// ---------------- embedding + positional encoding ----------------
__global__ void embed_kernel(const int* __restrict__ tgt,
                             const float* __restrict__ emb,
                             float* __restrict__ out)
{
    int row = blockIdx.x;
    int t   = row & (TLEN_ - 1);
    int tok = tgt[row];
    const float* e = emb + (size_t)tok * DMODEL;
    const float c = (float)(-9.210340371976184 / (double)DMODEL);
    for (int d = threadIdx.x; d < DMODEL; d += blockDim.x) {
        int k2 = d & ~1;
        float div = expf((float)k2 * c);
        float ang = (float)t * div;
        float pe  = (d & 1) ? cosf(ang) : sinf(ang);
        out[(size_t)row*DMODEL + d] = e[d] * 27.712812921102035f + pe;
    }
}

// ---------------- layernorm ----------------
__device__ __forceinline__ float blockReduceSum(float v)
{
    __shared__ float sh[9];
    int lane = threadIdx.x & 31, w = threadIdx.x >> 5;
    #pragma unroll
    for (int o = 16; o; o >>= 1) v += __shfl_xor_sync(0xffffffffu, v, o);
    __syncthreads();
    if (lane == 0) sh[w] = v;
    __syncthreads();
    if (threadIdx.x == 0) {
        float t = 0.f;
        #pragma unroll
        for (int i = 0; i < 8; i++) t += sh[i];
        sh[8] = t;
    }
    __syncthreads();
    return sh[8];
}

template<bool OUTH>
__global__ __launch_bounds__(256) void ln_kernel(const float* __restrict__ X,
                                                 const float* __restrict__ gam,
                                                 const float* __restrict__ bet,
                                                 void* __restrict__ Yv)
{
    int row = blockIdx.x;
    const float* x = X + (size_t)row * DMODEL;
    float s = 0.f;
    for (int d = threadIdx.x; d < DMODEL; d += 256) s += x[d];
    s = blockReduceSum(s);
    float mean = s / (float)DMODEL;
    float v = 0.f;
    for (int d = threadIdx.x; d < DMODEL; d += 256) { float t = x[d] - mean; v += t * t; }
    v = blockReduceSum(v);
    float inv = rsqrtf(v / (float)DMODEL + 1e-6f);
    for (int d = threadIdx.x; d < DMODEL; d += 256) {
        float y = (x[d] - mean) * inv * gam[d] + bet[d];
        if (OUTH) ((__half*)Yv)[(size_t)row*DMODEL + d] = __float2half_rn(y);
        else      ((float*)Yv)[(size_t)row*DMODEL + d] = y;
    }
}

// ---------------- fp16 tensor-core GEMM (4-stage cp.async + ldmatrix) --------
// C[M,N] = A[M,K] @ W[N,K]^T (+bias)(+gelu)(+resid), A/W fp16, acc fp32.
// 128xBN block tile (BN=128 or 64), BK=32 halves, 256 threads = 8 warps.
// BN=128: warp tile 32x64 (2x4 warp grid over cols? no: 4x2). BN=64: 32x32 (4x2).
// Row stride 40 halves: ldmatrix phase conflict-free.

#define HST 40

template<int BN, bool BIAS, bool RESID, bool GELU, bool OUTH>
__global__ __launch_bounds__(256, 2) void gemm_h(
    const __half* __restrict__ A, const __half* __restrict__ W,
    const float* __restrict__ bias, const float* __restrict__ Rm,
    void* __restrict__ Cv, int M, int N, int K)
{
    constexpr int ATILE  = 128*HST;          // halves
    constexpr int BTILE  = BN*HST;
    constexpr int HSTAGE = ATILE + BTILE;
    constexpr int NT  = BN/16;               // acc col-tiles (n8 pairs*2)
    constexpr int NTP = BN/32;               // ldmatrix col-pair count

    extern __shared__ __half sh[];
    const uint32_t sbase = (uint32_t)__cvta_generic_to_shared(sh);

    const int tid  = threadIdx.x;
    const int warp = tid >> 5, lane = tid & 31;
    const int gid  = lane >> 2, tig = lane & 3;
    const int brow = blockIdx.y * 128, bcol = blockIdx.x * BN;
    const int wr   = (warp >> 1) * 32;        // warp row offset (0,32,64,96)
    const int wc   = (warp & 1) * (BN/2);     // warp col offset

    const int subm   = lane >> 3;
    const int l8     = lane & 7;
    const int a_row  = wr + ((subm & 1) << 3) + l8;
    const int a_koff = (subm >> 1) << 3;
    const int b_row  = wc + ((subm >> 1) << 3) + l8;
    const int b_koff = (subm & 1) << 3;

    const __half* Abase = A + (size_t)brow * K;
    const __half* Wbase = W + (size_t)bcol * K;

    float acc[2][NT][4];
    #pragma unroll
    for (int mt = 0; mt < 2; mt++)
        #pragma unroll
        for (int nt = 0; nt < NT; nt++)
            #pragma unroll
            for (int r = 0; r < 4; r++) acc[mt][nt][r] = 0.f;

    const int niter = K >> 5;

    auto load_stage = [&](int it, int s) {
        __half* as = sh + s*HSTAGE;
        __half* bs = as + ATILE;
        #pragma unroll
        for (int i = 0; i < 2; i++) {
            int c = tid + i*256;
            int r = c >> 2, cc = c & 3;
            cp16h(as + r*HST + cc*8, Abase + (size_t)r*K + it*32 + cc*8);
        }
        #pragma unroll
        for (int i = 0; i < (BN >> 6); i++) {
            int c = tid + i*256;
            int r = c >> 2, cc = c & 3;
            cp16h(bs + r*HST + cc*8, Wbase + (size_t)r*K + it*32 + cc*8);
        }
        asm volatile("cp.async.commit_group;");
    };

    load_stage(0, 0);
    load_stage(1, 1);
    load_stage(2, 2);

    for (int it = 0; it < niter; it++) {
        if      (it + 3 <= niter) asm volatile("cp.async.wait_group 2;");
        else if (it + 2 == niter) asm volatile("cp.async.wait_group 1;");
        else                      asm volatile("cp.async.wait_group 0;");
        __syncthreads();

        if (it + 3 < niter) load_stage(it + 3, (it + 3) & 3);

        const uint32_t as_u = sbase + (uint32_t)((it & 3)*HSTAGE)*2;
        const uint32_t bs_u = as_u + ATILE*2;

        #pragma unroll
        for (int ksx = 0; ksx < 2; ksx++) {
            const int kb = ksx * 16;
            uint32_t afr[2][4];
            #pragma unroll
            for (int mt = 0; mt < 2; mt++)
                ldsm_x4(afr[mt], as_u + (uint32_t)((a_row + mt*16)*HST + kb + a_koff)*2);
            #pragma unroll
            for (int ntp = 0; ntp < NTP; ntp++) {
                uint32_t bfr[4];
                ldsm_x4(bfr, bs_u + (uint32_t)((b_row + ntp*16)*HST + kb + b_koff)*2);
                mma_f16(acc[0][2*ntp    ], afr[0], bfr    );
                mma_f16(acc[1][2*ntp    ], afr[1], bfr    );
                mma_f16(acc[0][2*ntp + 1], afr[0], bfr + 2);
                mma_f16(acc[1][2*ntp + 1], afr[1], bfr + 2);
            }
        }
    }

    #pragma unroll
    for (int mt = 0; mt < 2; mt++) {
        #pragma unroll
        for (int half = 0; half < 2; half++) {
            int row = brow + wr + mt*16 + gid + half*8;
            #pragma unroll
            for (int nt = 0; nt < NT; nt++) {
                int col = bcol + wc + nt*8 + 2*tig;
                float v0 = acc[mt][nt][half*2 + 0];
                float v1 = acc[mt][nt][half*2 + 1];
                if (BIAS) { v0 += bias[col]; v1 += bias[col+1]; }
                if (GELU) {
                    float u0 = v0, u1 = v1;
                    v0 = 0.5f*u0*(1.f + tanhf(0.7978845608028654f*(u0 + 0.044715f*u0*u0*u0)));
                    v1 = 0.5f*u1*(1.f + tanhf(0.7978845608028654f*(u1 + 0.044715f*u1*u1*u1)));
                }
                if (RESID) {
                    v0 += Rm[(size_t)row*N + col];
                    v1 += Rm[(size_t)row*N + col + 1];
                }
                if (OUTH) {
                    __half2 hv = __floats2half2_rn(v0, v1);
                    *(__half2*)&((__half*)Cv)[(size_t)row*N + col] = hv;
                } else {
                    *(float2*)&((float*)Cv)[(size_t)row*N + col] = make_float2(v0, v1);
                }
            }
        }
    }
}

#define GEMM_SMEM_128 (4*(128*HST + 128*HST)*2)   // 81920 B
#define GEMM_SMEM_64  (4*(128*HST +  64*HST)*2)   // 61440 B

// ---------------- fp16 tensor-core flash attention (Q-tile 128) ----------------
// 256 threads = 8 warps, 16 q rows each. 64-key tiles, DH=64.
// qs[128][72], ks[64][72], ps[128][72] (separate P buffer -> no S->PV barrier),
// V transposed into packed k-pair half2 vst2[64][36].
#define AQST 72
#define VST2 36
#define ATTN_SMEM ((128*AQST + 64*AQST + 128*AQST)*2 + 64*VST2*4)   // 55296 B

template<bool CAUSAL>
__global__ __launch_bounds__(256) void attn_h(
    const __half* __restrict__ Q, int qstride,
    const __half* __restrict__ Kp, int kstride,
    const __half* __restrict__ Vp, int vstride,
    const int*  __restrict__ tok, int klen,
    __half* __restrict__ O, int ostride)
{
    extern __shared__ char smraw[];
    __half*   qs   = (__half*)smraw;                         // [128][72]
    __half*   ks   = qs + 128*AQST;                          // [64][72]
    __half*   ps   = ks + 64*AQST;                           // [128][72]
    uint32_t* vst2 = (uint32_t*)(smraw + (128+64+128)*AQST*2); // [64][36]
    __shared__ int smask[64];

    const int tid  = threadIdx.x;
    const int warp = tid >> 5, lane = tid & 31;
    const int gid  = lane >> 2, tig = lane & 3;
    const int wrow = warp * 16;                  // 0..112
    const int qt = blockIdx.x, h = blockIdx.y, b = blockIdx.z;
    const int qbase = qt * 128;

    // ---- load Q tile (128 rows; scale by 0.125, exact in fp16)
    {
        int lr = tid >> 1;                       // 0..127
        int lc = (tid & 1) * 32;
        const __half* qp = Q + (size_t)(b*TLEN_ + qbase + lr)*qstride + h*DH_ + lc;
        const __half2 sc = __float2half2_rn(0.125f);
        #pragma unroll
        for (int j = 0; j < 4; j++) {
            uint4 raw = *(const uint4*)(qp + j*8);
            __half2* hv = (__half2*)&raw;
            hv[0] = __hmul2(hv[0], sc); hv[1] = __hmul2(hv[1], sc);
            hv[2] = __hmul2(hv[2], sc); hv[3] = __hmul2(hv[3], sc);
            *(uint4*)(qs + lr*AQST + lc + j*8) = raw;
        }
    }

    float m[2] = {-INFINITY, -INFINITY};
    float l[2] = {0.f, 0.f};
    float oacc[8][4];
    #pragma unroll
    for (int nt = 0; nt < 8; nt++)
        #pragma unroll
        for (int r = 0; r < 4; r++) oacc[nt][r] = 0.f;

    const int nkt = CAUSAL ? (2*qt + 2) : (klen >> 6);
    for (int kt = 0; kt < nkt; kt++) {
        __syncthreads();   // prev tile's S (ks) and PV (vst2) fully consumed

        // ---- K tile: 64 rows x 64 halves; 256 threads -> 16 halves each
        {
            int lr = tid >> 2;                   // 0..63
            int lc = (tid & 3) * 16;
            const __half* kp = Kp + (size_t)(b*klen + kt*64 + lr)*kstride + h*DH_ + lc;
            *(uint4*)(ks + lr*AQST + lc    ) = *(const uint4*)(kp    );
            *(uint4*)(ks + lr*AQST + lc + 8) = *(const uint4*)(kp + 8);
            if (tid < 64) smask[tid] = (tok[b*klen + kt*64 + tid] == 0);
        }

        // ---- V tile transposed: each thread 2 k-rows x 8 d
        {
            int vr = tid & 31;                   // k-pair
            int dbase = (tid >> 5) * 8;          // 0..56
            const __half* v0p = Vp + (size_t)(b*klen + kt*64 + 2*vr)*vstride + h*DH_ + dbase;
            const __half* v1p = v0p + vstride;
            __half va[8], vb[8];
            *(uint4*)&va[0] = *(const uint4*)v0p;
            *(uint4*)&vb[0] = *(const uint4*)v1p;
            #pragma unroll
            for (int j = 0; j < 8; j++) {
                __half2 p = __halves2half2(va[j], vb[j]);  // low = even k
                vst2[(dbase + j)*VST2 + vr] = *(uint32_t*)&p;
            }
        }
        __syncthreads();

        // ---- S = Q @ K^T
        float sfr[8][4];
        #pragma unroll
        for (int nt = 0; nt < 8; nt++)
            #pragma unroll
            for (int r = 0; r < 4; r++) sfr[nt][r] = 0.f;

        #pragma unroll
        for (int ks16 = 0; ks16 < 4; ks16++) {
            const int kb = ks16*16;
            uint32_t a[4];
            a[0] = ldsm_u32(&qs[(wrow+gid  )*AQST + kb + 2*tig    ]);
            a[1] = ldsm_u32(&qs[(wrow+gid+8)*AQST + kb + 2*tig    ]);
            a[2] = ldsm_u32(&qs[(wrow+gid  )*AQST + kb + 2*tig + 8]);
            a[3] = ldsm_u32(&qs[(wrow+gid+8)*AQST + kb + 2*tig + 8]);
            #pragma unroll
            for (int nt = 0; nt < 8; nt++) {
                uint32_t bf[2];
                bf[0] = ldsm_u32(&ks[(nt*8+gid)*AQST + kb + 2*tig    ]);
                bf[1] = ldsm_u32(&ks[(nt*8+gid)*AQST + kb + 2*tig + 8]);
                mma_f16(sfr[nt], a, bf);
            }
        }

        // ---- mask (replace with -1e18, matching reference)
        #pragma unroll
        for (int nt = 0; nt < 8; nt++) {
            #pragma unroll
            for (int e = 0; e < 4; e++) {
                int cl = nt*8 + 2*tig + (e & 1);
                int rowg = qbase + wrow + gid + (e >> 1)*8;
                int colg = kt*64 + cl;
                bool msk = (smask[cl] != 0) || (CAUSAL && colg > rowg);
                if (msk) sfr[nt][e] = -1e18f;
            }
        }

        // ---- online softmax
        #pragma unroll
        for (int h2 = 0; h2 < 2; h2++) {
            float rm = -INFINITY;
            #pragma unroll
            for (int nt = 0; nt < 8; nt++)
                rm = fmaxf(rm, fmaxf(sfr[nt][h2*2], sfr[nt][h2*2+1]));
            rm = fmaxf(rm, __shfl_xor_sync(0xffffffffu, rm, 1));
            rm = fmaxf(rm, __shfl_xor_sync(0xffffffffu, rm, 2));
            float nm = fmaxf(m[h2], rm);
            float alpha = __expf(m[h2] - nm);
            float rs = 0.f;
            #pragma unroll
            for (int nt = 0; nt < 8; nt++) {
                float p0 = __expf(sfr[nt][h2*2]   - nm);
                float p1 = __expf(sfr[nt][h2*2+1] - nm);
                sfr[nt][h2*2] = p0; sfr[nt][h2*2+1] = p1;
                rs += p0 + p1;
            }
            rs += __shfl_xor_sync(0xffffffffu, rs, 1);
            rs += __shfl_xor_sync(0xffffffffu, rs, 2);
            l[h2] = l[h2]*alpha + rs;
            m[h2] = nm;
            #pragma unroll
            for (int nt = 0; nt < 8; nt++) {
                oacc[nt][h2*2]   *= alpha;
                oacc[nt][h2*2+1] *= alpha;
            }
        }

        // ---- write P (fp16) into own buffer; warp-private rows -> no block sync
        #pragma unroll
        for (int nt = 0; nt < 8; nt++) {
            #pragma unroll
            for (int h2 = 0; h2 < 2; h2++) {
                __half2 hp = __floats2half2_rn(sfr[nt][h2*2], sfr[nt][h2*2+1]);
                *(__half2*)&ps[(wrow + gid + h2*8)*AQST + nt*8 + 2*tig] = hp;
            }
        }
        __syncwarp();

        // ---- O += P @ V (B from transposed vst2)
        #pragma unroll
        for (int ks16 = 0; ks16 < 4; ks16++) {
            const int kb  = ks16*16;
            const int kb2 = ks16*8;
            uint32_t a[4];
            a[0] = ldsm_u32(&ps[(wrow+gid  )*AQST + kb + 2*tig    ]);
            a[1] = ldsm_u32(&ps[(wrow+gid+8)*AQST + kb + 2*tig    ]);
            a[2] = ldsm_u32(&ps[(wrow+gid  )*AQST + kb + 2*tig + 8]);
            a[3] = ldsm_u32(&ps[(wrow+gid+8)*AQST + kb + 2*tig + 8]);
            #pragma unroll
            for (int nt = 0; nt < 8; nt++) {
                uint32_t bf[2];
                bf[0] = vst2[(nt*8+gid)*VST2 + kb2 + tig    ];
                bf[1] = vst2[(nt*8+gid)*VST2 + kb2 + tig + 4];
                mma_f16(oacc[nt], a, bf);
            }
        }
    }

    // ---- epilogue: O = fp16(acc / l)
    float inv0 = 1.f / l[0];
    float inv1 = 1.f / l[1];
    size_t r0 = (size_t)(b*TLEN_ + qbase + wrow + gid)*ostride + h*DH_;
    size_t r1 = r0 + (size_t)8*ostride;
    #pragma unroll
    for (int nt = 0; nt < 8; nt++) {
        int col = nt*8 + 2*tig;
        __half2 o0 = __floats2half2_rn(oacc[nt][0]*inv0, oacc[nt][1]*inv0);
        __half2 o1 = __floats2half2_rn(oacc[nt][2]*inv1, oacc[nt][3]*inv1);
        *(__half2*)&O[r0 + col] = o0;
        *(__half2*)&O[r1 + col] = o1;
    }
}

// ---------------- host orchestration ----------------
extern "C" void kernel_launch(void* const* d_in, const int* in_sizes, int n_in,
                              void* d_out, int out_size)
{
    (void)in_sizes; (void)n_in; (void)out_size;
    const int*   tgt    = (const int*)  d_in[0];
    const int*   src    = (const int*)  d_in[1];
    const float* memory = (const float*)d_in[2];
    const float* emb    = (const float*)d_in[3];
    const float* sa_w   = (const float*)d_in[4];
    const float* sa_b   = (const float*)d_in[5];
    const float* ca_w   = (const float*)d_in[6];
    const float* ca_b   = (const float*)d_in[7];
    const float* ln_g   = (const float*)d_in[8];
    const float* ln_b   = (const float*)d_in[9];
    const float* ff_w1  = (const float*)d_in[10];
    const float* ff_b1  = (const float*)d_in[11];
    const float* ff_w2  = (const float*)d_in[12];
    const float* ff_b2  = (const float*)d_in[13];
    const float* out_g  = (const float*)d_in[14];
    const float* out_b  = (const float*)d_in[15];
    float* out = (float*)d_out;

    float *res, *res2;
    __half *lnb, *qkv, *kv, *ctx, *ff, *wsa, *wca, *w1, *w2, *mem;
    cudaGetSymbolAddress((void**)&res,  g_res);
    cudaGetSymbolAddress((void**)&res2, g_res2);
    cudaGetSymbolAddress((void**)&lnb,  g_lnb);
    cudaGetSymbolAddress((void**)&qkv,  g_qkv);
    cudaGetSymbolAddress((void**)&kv,   g_kv);
    cudaGetSymbolAddress((void**)&ctx,  g_ctx);
    cudaGetSymbolAddress((void**)&ff,   g_ff);
    cudaGetSymbolAddress((void**)&wsa,  g_wsa);
    cudaGetSymbolAddress((void**)&wca,  g_wca);
    cudaGetSymbolAddress((void**)&w1,   g_w1);
    cudaGetSymbolAddress((void**)&w2,   g_w2);
    cudaGetSymbolAddress((void**)&mem,  g_mem);

    cudaFuncSetAttribute(attn_h<true>,  cudaFuncAttributeMaxDynamicSharedMemorySize, ATTN_SMEM);
    cudaFuncSetAttribute(attn_h<false>, cudaFuncAttributeMaxDynamicSharedMemorySize, ATTN_SMEM);
    cudaFuncSetAttribute((gemm_h<128,true,false,false,true >), cudaFuncAttributeMaxDynamicSharedMemorySize, GEMM_SMEM_128);
    cudaFuncSetAttribute((gemm_h<128,true,false,true ,true >), cudaFuncAttributeMaxDynamicSharedMemorySize, GEMM_SMEM_128);
    cudaFuncSetAttribute((gemm_h<64 ,true,true ,false,false>), cudaFuncAttributeMaxDynamicSharedMemorySize, GEMM_SMEM_64);
    cudaFuncSetAttribute((gemm_h<64 ,true,false,false,true >), cudaFuncAttributeMaxDynamicSharedMemorySize, GEMM_SMEM_64);

    embed_kernel<<<BT_, 256>>>(tgt, emb, res);
    {
        const size_t NW = (size_t)NL*4*DMODEL*DMODEL/4;
        const size_t NF = (size_t)NL*DFF_*DMODEL/4;
        const size_t NM = (size_t)BS_*DMODEL/4;
        const size_t total = 2*NW + 2*NF + NM;
        conv_all_kernel<<<(unsigned)((total + 255)/256), 256>>>(
            (const float4*)sa_w, (const float4*)ca_w,
            (const float4*)ff_w1, (const float4*)ff_w2, (const float4*)memory,
            wsa, wca, w1, w2, mem);
    }

    const dim3 g2304 (3*DMODEL/128, BT_/128);   // BN=128
    const dim3 g1536 (2*DMODEL/128, BS_/128);   // BN=128
    const dim3 g3072 (DFF_/128, BT_/128);       // BN=128
    const dim3 g768t (DMODEL/64, BT_/128);      // BN=64 -> 384 CTAs
    const dim3 attn_grid(TLEN_/128, NH, BB);

    for (int i = 0; i < NL; i++) {
        const __half* saw = wsa + (size_t)i*4*DMODEL*DMODEL;
        const float*  sab = sa_b + (size_t)i*4*DMODEL;
        const __half* caw = wca + (size_t)i*4*DMODEL*DMODEL;
        const float*  cab = ca_b + (size_t)i*4*DMODEL;
        const float*  lg  = ln_g + (size_t)i*3*DMODEL;
        const float*  lb  = ln_b + (size_t)i*3*DMODEL;

        // ----- self attention -----
        ln_kernel<true><<<BT_, 256>>>(res, lg, lb, lnb);
        gemm_h<128,true,false,false,true><<<g2304, 256, GEMM_SMEM_128>>>(lnb, saw, sab, nullptr, qkv,
                                                  BT_, 3*DMODEL, DMODEL);
        attn_h<true><<<attn_grid, 256, ATTN_SMEM>>>(
            qkv, 3*DMODEL, qkv + DMODEL, 3*DMODEL, qkv + 2*DMODEL, 3*DMODEL,
            tgt, TLEN_, ctx, DMODEL);
        gemm_h<64,true,true,false,false><<<g768t, 256, GEMM_SMEM_64>>>(ctx, saw + (size_t)3*DMODEL*DMODEL,
                                                sab + 3*DMODEL, res, res2,
                                                BT_, DMODEL, DMODEL);

        // ----- cross attention -----
        ln_kernel<true><<<BT_, 256>>>(res2, lg + DMODEL, lb + DMODEL, lnb);
        gemm_h<64,true,false,false,true><<<g768t, 256, GEMM_SMEM_64>>>(lnb, caw, cab, nullptr, qkv,
                                                 BT_, DMODEL, DMODEL);
        gemm_h<128,true,false,false,true><<<g1536, 256, GEMM_SMEM_128>>>(mem, caw + (size_t)DMODEL*DMODEL,
                                                  cab + DMODEL, nullptr, kv,
                                                  BS_, 2*DMODEL, DMODEL);
        attn_h<false><<<attn_grid, 256, ATTN_SMEM>>>(
            qkv, DMODEL, kv, 2*DMODEL, kv + DMODEL, 2*DMODEL,
            src, SLEN_, ctx, DMODEL);
        gemm_h<64,true,true,false,false><<<g768t, 256, GEMM_SMEM_64>>>(ctx, caw + (size_t)3*DMODEL*DMODEL,
                                                cab + 3*DMODEL, res2, res,
                                                BT_, DMODEL, DMODEL);

        // ----- FFN -----
        ln_kernel<true><<<BT_, 256>>>(res, lg + 2*DMODEL, lb + 2*DMODEL, lnb);
        gemm_h<128,true,false,true,true><<<g3072, 256, GEMM_SMEM_128>>>(lnb, w1 + (size_t)i*DFF_*DMODEL,
                                                 ff_b1 + (size_t)i*DFF_, nullptr, ff,
                                                 BT_, DFF_, DMODEL);
        gemm_h<64,true,true,false,false><<<g768t, 256, GEMM_SMEM_64>>>(ff, w2 + (size_t)i*DMODEL*DFF_,
                                                ff_b2 + (size_t)i*DMODEL, res, res2,
                                                BT_, DMODEL, DFF_);

        float* tmp = res; res = res2; res2 = tmp;
    }

    ln_kernel<false><<<BT_, 256>>>(res, out_g, out_b, out);
}

// round 17
// speedup vs baseline: 1.1595x; 1.0485x over previous
#include <cuda_runtime.h>
#include <cuda_fp16.h>
#include <math.h>
#include <stdint.h>

// ---------------- problem constants ----------------
#define NL    6
#define DMODEL 768
#define NH    12
#define DFF_  3072
#define BB    8
#define TLEN_ 512
#define SLEN_ 512
#define DH_   64
#define BT_   (BB*TLEN_)   // 4096 target tokens
#define BS_   (BB*SLEN_)   // 4096 source tokens

// ---------------- scratch (device globals: allocation-free) ----------------
__device__ float  g_res [BT_*DMODEL];
__device__ float  g_res2[BT_*DMODEL];
__device__ __half g_lnb [BT_*DMODEL];
__device__ __half g_qkv [BT_*3*DMODEL];
__device__ __half g_kv  [BS_*2*DMODEL];
__device__ __half g_ctx [BT_*DMODEL];
__device__ __half g_ff  [BT_*DFF_];
// fp16 pre-converted weights / memory
__device__ __half g_wsa[(size_t)NL*4*DMODEL*DMODEL];
__device__ __half g_wca[(size_t)NL*4*DMODEL*DMODEL];
__device__ __half g_w1 [(size_t)NL*DFF_*DMODEL];
__device__ __half g_w2 [(size_t)NL*DMODEL*DFF_];
__device__ __half g_mem[(size_t)BS_*DMODEL];

// ---------------- fp16 mma helper ----------------
__device__ __forceinline__ void mma_f16(float c[4], const uint32_t a[4], const uint32_t b[2])
{
    asm volatile(
        "mma.sync.aligned.m16n8k16.row.col.f32.f16.f16.f32 "
        "{%0,%1,%2,%3}, {%4,%5,%6,%7}, {%8,%9}, {%0,%1,%2,%3};"
        : "+f"(c[0]), "+f"(c[1]), "+f"(c[2]), "+f"(c[3])
        : "r"(a[0]), "r"(a[1]), "r"(a[2]), "r"(a[3]), "r"(b[0]), "r"(b[1]));
}

// ldmatrix x4: 4x 8x8 b16 matrices; lane i supplies row address for matrix i>>3
__device__ __forceinline__ void ldsm_x4(uint32_t r[4], uint32_t saddr)
{
    asm volatile(
        "ldmatrix.sync.aligned.m8n8.x4.shared.b16 {%0,%1,%2,%3}, [%4];"
        : "=r"(r[0]), "=r"(r[1]), "=r"(r[2]), "=r"(r[3]) : "r"(saddr));
}

__device__ __forceinline__ void cp16h(__half* dst, const __half* src)
{
    uint32_t s = (uint32_t)__cvta_generic_to_shared(dst);
    asm volatile("cp.async.cg.shared.global [%0], [%1], 16;" :: "r"(s), "l"(src));
}

__device__ __forceinline__ uint32_t ldsm_u32(const __half* p)
{
    return *(const uint32_t*)p;
}

// ---------------- fused fp16 pre-convert kernel ----------------
__global__ void conv_all_kernel(const float4* __restrict__ sa, const float4* __restrict__ ca,
                                const float4* __restrict__ f1, const float4* __restrict__ f2,
                                const float4* __restrict__ mm,
                                __half* __restrict__ osa, __half* __restrict__ oca,
                                __half* __restrict__ of1, __half* __restrict__ of2,
                                __half* __restrict__ omm)
{
    const size_t NW = (size_t)NL*4*DMODEL*DMODEL/4;
    const size_t NF = (size_t)NL*DFF_*DMODEL/4;
    const size_t NM = (size_t)BS_*DMODEL/4;
    size_t i = (size_t)blockIdx.x*256 + threadIdx.x;
    const float4* src; __half* dst; size_t off;
    if      (i < NW)               { src = sa; dst = osa; off = i; }
    else if (i < 2*NW)             { src = ca; dst = oca; off = i - NW; }
    else if (i < 2*NW + NF)        { src = f1; dst = of1; off = i - 2*NW; }
    else if (i < 2*NW + 2*NF)      { src = f2; dst = of2; off = i - 2*NW - NF; }
    else if (i < 2*NW + 2*NF + NM) { src = mm; dst = omm; off = i - 2*NW - 2*NF; }
    else return;
    float4 v = src[off];
    __half2 h01 = __floats2half2_rn(v.x, v.y);
    __half2 h23 = __floats2half2_rn(v.z, v.w);
    uint2 st;
    st.x = *(uint32_t*)&h01;
    st.y = *(uint32_t*)&h23;
    *(uint2*)(dst + off*4) = st;
}

// ---------------- embedding + positional encoding ----------------
__global__ void embed_kernel(const int* __restrict__ tgt,
                             const float* __restrict__ emb,
                             float* __restrict__ out)
{
    int row = blockIdx.x;
    int t   = row & (TLEN_ - 1);
    int tok = tgt[row];
    const float* e = emb + (size_t)tok * DMODEL;
    const float c = (float)(-9.210340371976184 / (double)DMODEL);
    for (int d = threadIdx.x; d < DMODEL; d += blockDim.x) {
        int k2 = d & ~1;
        float div = expf((float)k2 * c);
        float ang = (float)t * div;
        float pe  = (d & 1) ? cosf(ang) : sinf(ang);
        out[(size_t)row*DMODEL + d] = e[d] * 27.712812921102035f + pe;
    }
}

// ---------------- warp-per-row layernorm ----------------
// 256 threads = 8 warps = 8 rows/block. Row (768 floats) lives in registers
// (6 float4/lane); warp-shuffle reductions only; 1 global read + 1 write.
template<bool OUTH>
__global__ __launch_bounds__(256) void ln_kernel(const float* __restrict__ X,
                                                 const float* __restrict__ gam,
                                                 const float* __restrict__ bet,
                                                 void* __restrict__ Yv)
{
    const int lane = threadIdx.x & 31;
    const int row  = blockIdx.x * 8 + (threadIdx.x >> 5);
    const float* x = X + (size_t)row * DMODEL;

    float4 v[6];
    #pragma unroll
    for (int j = 0; j < 6; j++)
        v[j] = *(const float4*)(x + (j*32 + lane)*4);

    float s = 0.f;
    #pragma unroll
    for (int j = 0; j < 6; j++) s += v[j].x + v[j].y + v[j].z + v[j].w;
    #pragma unroll
    for (int o = 16; o; o >>= 1) s += __shfl_xor_sync(0xffffffffu, s, o);
    const float mean = s * (1.f/(float)DMODEL);

    float var = 0.f;
    #pragma unroll
    for (int j = 0; j < 6; j++) {
        float a = v[j].x - mean, b = v[j].y - mean,
              c = v[j].z - mean, d = v[j].w - mean;
        var += a*a + b*b + c*c + d*d;
    }
    #pragma unroll
    for (int o = 16; o; o >>= 1) var += __shfl_xor_sync(0xffffffffu, var, o);
    const float inv = rsqrtf(var * (1.f/(float)DMODEL) + 1e-6f);

    #pragma unroll
    for (int j = 0; j < 6; j++) {
        const int d4 = (j*32 + lane)*4;
        float4 g = *(const float4*)(gam + d4);
        float4 bb = *(const float4*)(bet + d4);
        float y0 = (v[j].x - mean)*inv*g.x + bb.x;
        float y1 = (v[j].y - mean)*inv*g.y + bb.y;
        float y2 = (v[j].z - mean)*inv*g.z + bb.z;
        float y3 = (v[j].w - mean)*inv*g.w + bb.w;
        if (OUTH) {
            __half2 h01 = __floats2half2_rn(y0, y1);
            __half2 h23 = __floats2half2_rn(y2, y3);
            uint2 st; st.x = *(uint32_t*)&h01; st.y = *(uint32_t*)&h23;
            *(uint2*)&((__half*)Yv)[(size_t)row*DMODEL + d4] = st;
        } else {
            *(float4*)&((float*)Yv)[(size_t)row*DMODEL + d4] =
                make_float4(y0, y1, y2, y3);
        }
    }
}

// ---------------- fp16 tensor-core GEMM (4-stage cp.async + ldmatrix) --------
// C[M,N] = A[M,K] @ W[N,K]^T (+bias)(+gelu)(+resid), A/W fp16, acc fp32.
// 128xBN block tile (BN=128 or 64), BK=32 halves, 256 threads = 8 warps.
// Row stride 40 halves: ldmatrix phase conflict-free.

#define HST 40

template<int BN, bool BIAS, bool RESID, bool GELU, bool OUTH>
__global__ __launch_bounds__(256, 2) void gemm_h(
    const __half* __restrict__ A, const __half* __restrict__ W,
    const float* __restrict__ bias, const float* __restrict__ Rm,
    void* __restrict__ Cv, int M, int N, int K)
{
    constexpr int ATILE  = 128*HST;          // halves
    constexpr int BTILE  = BN*HST;
    constexpr int HSTAGE = ATILE + BTILE;
    constexpr int NT  = BN/16;
    constexpr int NTP = BN/32;

    extern __shared__ __half sh[];
    const uint32_t sbase = (uint32_t)__cvta_generic_to_shared(sh);

    const int tid  = threadIdx.x;
    const int warp = tid >> 5, lane = tid & 31;
    const int gid  = lane >> 2, tig = lane & 3;
    const int brow = blockIdx.y * 128, bcol = blockIdx.x * BN;
    const int wr   = (warp >> 1) * 32;
    const int wc   = (warp & 1) * (BN/2);

    const int subm   = lane >> 3;
    const int l8     = lane & 7;
    const int a_row  = wr + ((subm & 1) << 3) + l8;
    const int a_koff = (subm >> 1) << 3;
    const int b_row  = wc + ((subm >> 1) << 3) + l8;
    const int b_koff = (subm & 1) << 3;

    const __half* Abase = A + (size_t)brow * K;
    const __half* Wbase = W + (size_t)bcol * K;

    float acc[2][NT][4];
    #pragma unroll
    for (int mt = 0; mt < 2; mt++)
        #pragma unroll
        for (int nt = 0; nt < NT; nt++)
            #pragma unroll
            for (int r = 0; r < 4; r++) acc[mt][nt][r] = 0.f;

    const int niter = K >> 5;

    auto load_stage = [&](int it, int s) {
        __half* as = sh + s*HSTAGE;
        __half* bs = as + ATILE;
        #pragma unroll
        for (int i = 0; i < 2; i++) {
            int c = tid + i*256;
            int r = c >> 2, cc = c & 3;
            cp16h(as + r*HST + cc*8, Abase + (size_t)r*K + it*32 + cc*8);
        }
        #pragma unroll
        for (int i = 0; i < (BN >> 6); i++) {
            int c = tid + i*256;
            int r = c >> 2, cc = c & 3;
            cp16h(bs + r*HST + cc*8, Wbase + (size_t)r*K + it*32 + cc*8);
        }
        asm volatile("cp.async.commit_group;");
    };

    load_stage(0, 0);
    load_stage(1, 1);
    load_stage(2, 2);

    for (int it = 0; it < niter; it++) {
        if      (it + 3 <= niter) asm volatile("cp.async.wait_group 2;");
        else if (it + 2 == niter) asm volatile("cp.async.wait_group 1;");
        else                      asm volatile("cp.async.wait_group 0;");
        __syncthreads();

        if (it + 3 < niter) load_stage(it + 3, (it + 3) & 3);

        const uint32_t as_u = sbase + (uint32_t)((it & 3)*HSTAGE)*2;
        const uint32_t bs_u = as_u + ATILE*2;

        #pragma unroll
        for (int ksx = 0; ksx < 2; ksx++) {
            const int kb = ksx * 16;
            uint32_t afr[2][4];
            #pragma unroll
            for (int mt = 0; mt < 2; mt++)
                ldsm_x4(afr[mt], as_u + (uint32_t)((a_row + mt*16)*HST + kb + a_koff)*2);
            #pragma unroll
            for (int ntp = 0; ntp < NTP; ntp++) {
                uint32_t bfr[4];
                ldsm_x4(bfr, bs_u + (uint32_t)((b_row + ntp*16)*HST + kb + b_koff)*2);
                mma_f16(acc[0][2*ntp    ], afr[0], bfr    );
                mma_f16(acc[1][2*ntp    ], afr[1], bfr    );
                mma_f16(acc[0][2*ntp + 1], afr[0], bfr + 2);
                mma_f16(acc[1][2*ntp + 1], afr[1], bfr + 2);
            }
        }
    }

    #pragma unroll
    for (int mt = 0; mt < 2; mt++) {
        #pragma unroll
        for (int half = 0; half < 2; half++) {
            int row = brow + wr + mt*16 + gid + half*8;
            #pragma unroll
            for (int nt = 0; nt < NT; nt++) {
                int col = bcol + wc + nt*8 + 2*tig;
                float v0 = acc[mt][nt][half*2 + 0];
                float v1 = acc[mt][nt][half*2 + 1];
                if (BIAS) { v0 += bias[col]; v1 += bias[col+1]; }
                if (GELU) {
                    float u0 = v0, u1 = v1;
                    v0 = 0.5f*u0*(1.f + tanhf(0.7978845608028654f*(u0 + 0.044715f*u0*u0*u0)));
                    v1 = 0.5f*u1*(1.f + tanhf(0.7978845608028654f*(u1 + 0.044715f*u1*u1*u1)));
                }
                if (RESID) {
                    v0 += Rm[(size_t)row*N + col];
                    v1 += Rm[(size_t)row*N + col + 1];
                }
                if (OUTH) {
                    __half2 hv = __floats2half2_rn(v0, v1);
                    *(__half2*)&((__half*)Cv)[(size_t)row*N + col] = hv;
                } else {
                    *(float2*)&((float*)Cv)[(size_t)row*N + col] = make_float2(v0, v1);
                }
            }
        }
    }
}

#define GEMM_SMEM_128 (4*(128*HST + 128*HST)*2)   // 81920 B
#define GEMM_SMEM_64  (4*(128*HST +  64*HST)*2)   // 61440 B

// ---------------- fp16 tensor-core flash attention (Q-tile 128) ----------------
#define AQST 72
#define VST2 36
#define ATTN_SMEM ((128*AQST + 64*AQST + 128*AQST)*2 + 64*VST2*4)   // 55296 B

template<bool CAUSAL>
__global__ __launch_bounds__(256) void attn_h(
    const __half* __restrict__ Q, int qstride,
    const __half* __restrict__ Kp, int kstride,
    const __half* __restrict__ Vp, int vstride,
    const int*  __restrict__ tok, int klen,
    __half* __restrict__ O, int ostride)
{
    extern __shared__ char smraw[];
    __half*   qs   = (__half*)smraw;                         // [128][72]
    __half*   ks   = qs + 128*AQST;                          // [64][72]
    __half*   ps   = ks + 64*AQST;                           // [128][72]
    uint32_t* vst2 = (uint32_t*)(smraw + (128+64+128)*AQST*2); // [64][36]
    __shared__ int smask[64];

    const int tid  = threadIdx.x;
    const int warp = tid >> 5, lane = tid & 31;
    const int gid  = lane >> 2, tig = lane & 3;
    const int wrow = warp * 16;
    const int qt = blockIdx.x, h = blockIdx.y, b = blockIdx.z;
    const int qbase = qt * 128;

    {
        int lr = tid >> 1;
        int lc = (tid & 1) * 32;
        const __half* qp = Q + (size_t)(b*TLEN_ + qbase + lr)*qstride + h*DH_ + lc;
        const __half2 sc = __float2half2_rn(0.125f);
        #pragma unroll
        for (int j = 0; j < 4; j++) {
            uint4 raw = *(const uint4*)(qp + j*8);
            __half2* hv = (__half2*)&raw;
            hv[0] = __hmul2(hv[0], sc); hv[1] = __hmul2(hv[1], sc);
            hv[2] = __hmul2(hv[2], sc); hv[3] = __hmul2(hv[3], sc);
            *(uint4*)(qs + lr*AQST + lc + j*8) = raw;
        }
    }

    float m[2] = {-INFINITY, -INFINITY};
    float l[2] = {0.f, 0.f};
    float oacc[8][4];
    #pragma unroll
    for (int nt = 0; nt < 8; nt++)
        #pragma unroll
        for (int r = 0; r < 4; r++) oacc[nt][r] = 0.f;

    const int nkt = CAUSAL ? (2*qt + 2) : (klen >> 6);
    for (int kt = 0; kt < nkt; kt++) {
        __syncthreads();

        {
            int lr = tid >> 2;
            int lc = (tid & 3) * 16;
            const __half* kp = Kp + (size_t)(b*klen + kt*64 + lr)*kstride + h*DH_ + lc;
            *(uint4*)(ks + lr*AQST + lc    ) = *(const uint4*)(kp    );
            *(uint4*)(ks + lr*AQST + lc + 8) = *(const uint4*)(kp + 8);
            if (tid < 64) smask[tid] = (tok[b*klen + kt*64 + tid] == 0);
        }

        {
            int vr = tid & 31;
            int dbase = (tid >> 5) * 8;
            const __half* v0p = Vp + (size_t)(b*klen + kt*64 + 2*vr)*vstride + h*DH_ + dbase;
            const __half* v1p = v0p + vstride;
            __half va[8], vb[8];
            *(uint4*)&va[0] = *(const uint4*)v0p;
            *(uint4*)&vb[0] = *(const uint4*)v1p;
            #pragma unroll
            for (int j = 0; j < 8; j++) {
                __half2 p = __halves2half2(va[j], vb[j]);
                vst2[(dbase + j)*VST2 + vr] = *(uint32_t*)&p;
            }
        }
        __syncthreads();

        float sfr[8][4];
        #pragma unroll
        for (int nt = 0; nt < 8; nt++)
            #pragma unroll
            for (int r = 0; r < 4; r++) sfr[nt][r] = 0.f;

        #pragma unroll
        for (int ks16 = 0; ks16 < 4; ks16++) {
            const int kb = ks16*16;
            uint32_t a[4];
            a[0] = ldsm_u32(&qs[(wrow+gid  )*AQST + kb + 2*tig    ]);
            a[1] = ldsm_u32(&qs[(wrow+gid+8)*AQST + kb + 2*tig    ]);
            a[2] = ldsm_u32(&qs[(wrow+gid  )*AQST + kb + 2*tig + 8]);
            a[3] = ldsm_u32(&qs[(wrow+gid+8)*AQST + kb + 2*tig + 8]);
            #pragma unroll
            for (int nt = 0; nt < 8; nt++) {
                uint32_t bf[2];
                bf[0] = ldsm_u32(&ks[(nt*8+gid)*AQST + kb + 2*tig    ]);
                bf[1] = ldsm_u32(&ks[(nt*8+gid)*AQST + kb + 2*tig + 8]);
                mma_f16(sfr[nt], a, bf);
            }
        }

        #pragma unroll
        for (int nt = 0; nt < 8; nt++) {
            #pragma unroll
            for (int e = 0; e < 4; e++) {
                int cl = nt*8 + 2*tig + (e & 1);
                int rowg = qbase + wrow + gid + (e >> 1)*8;
                int colg = kt*64 + cl;
                bool msk = (smask[cl] != 0) || (CAUSAL && colg > rowg);
                if (msk) sfr[nt][e] = -1e18f;
            }
        }

        #pragma unroll
        for (int h2 = 0; h2 < 2; h2++) {
            float rm = -INFINITY;
            #pragma unroll
            for (int nt = 0; nt < 8; nt++)
                rm = fmaxf(rm, fmaxf(sfr[nt][h2*2], sfr[nt][h2*2+1]));
            rm = fmaxf(rm, __shfl_xor_sync(0xffffffffu, rm, 1));
            rm = fmaxf(rm, __shfl_xor_sync(0xffffffffu, rm, 2));
            float nm = fmaxf(m[h2], rm);
            float alpha = __expf(m[h2] - nm);
            float rs = 0.f;
            #pragma unroll
            for (int nt = 0; nt < 8; nt++) {
                float p0 = __expf(sfr[nt][h2*2]   - nm);
                float p1 = __expf(sfr[nt][h2*2+1] - nm);
                sfr[nt][h2*2] = p0; sfr[nt][h2*2+1] = p1;
                rs += p0 + p1;
            }
            rs += __shfl_xor_sync(0xffffffffu, rs, 1);
            rs += __shfl_xor_sync(0xffffffffu, rs, 2);
            l[h2] = l[h2]*alpha + rs;
            m[h2] = nm;
            #pragma unroll
            for (int nt = 0; nt < 8; nt++) {
                oacc[nt][h2*2]   *= alpha;
                oacc[nt][h2*2+1] *= alpha;
            }
        }

        #pragma unroll
        for (int nt = 0; nt < 8; nt++) {
            #pragma unroll
            for (int h2 = 0; h2 < 2; h2++) {
                __half2 hp = __floats2half2_rn(sfr[nt][h2*2], sfr[nt][h2*2+1]);
                *(__half2*)&ps[(wrow + gid + h2*8)*AQST + nt*8 + 2*tig] = hp;
            }
        }
        __syncwarp();

        #pragma unroll
        for (int ks16 = 0; ks16 < 4; ks16++) {
            const int kb  = ks16*16;
            const int kb2 = ks16*8;
            uint32_t a[4];
            a[0] = ldsm_u32(&ps[(wrow+gid  )*AQST + kb + 2*tig    ]);
            a[1] = ldsm_u32(&ps[(wrow+gid+8)*AQST + kb + 2*tig    ]);
            a[2] = ldsm_u32(&ps[(wrow+gid  )*AQST + kb + 2*tig + 8]);
            a[3] = ldsm_u32(&ps[(wrow+gid+8)*AQST + kb + 2*tig + 8]);
            #pragma unroll
            for (int nt = 0; nt < 8; nt++) {
                uint32_t bf[2];
                bf[0] = vst2[(nt*8+gid)*VST2 + kb2 + tig    ];
                bf[1] = vst2[(nt*8+gid)*VST2 + kb2 + tig + 4];
                mma_f16(oacc[nt], a, bf);
            }
        }
    }

    float inv0 = 1.f / l[0];
    float inv1 = 1.f / l[1];
    size_t r0 = (size_t)(b*TLEN_ + qbase + wrow + gid)*ostride + h*DH_;
    size_t r1 = r0 + (size_t)8*ostride;
    #pragma unroll
    for (int nt = 0; nt < 8; nt++) {
        int col = nt*8 + 2*tig;
        __half2 o0 = __floats2half2_rn(oacc[nt][0]*inv0, oacc[nt][1]*inv0);
        __half2 o1 = __floats2half2_rn(oacc[nt][2]*inv1, oacc[nt][3]*inv1);
        *(__half2*)&O[r0 + col] = o0;
        *(__half2*)&O[r1 + col] = o1;
    }
}

// ---------------- host orchestration ----------------
extern "C" void kernel_launch(void* const* d_in, const int* in_sizes, int n_in,
                              void* d_out, int out_size)
{
    (void)in_sizes; (void)n_in; (void)out_size;
    const int*   tgt    = (const int*)  d_in[0];
    const int*   src    = (const int*)  d_in[1];
    const float* memory = (const float*)d_in[2];
    const float* emb    = (const float*)d_in[3];
    const float* sa_w   = (const float*)d_in[4];
    const float* sa_b   = (const float*)d_in[5];
    const float* ca_w   = (const float*)d_in[6];
    const float* ca_b   = (const float*)d_in[7];
    const float* ln_g   = (const float*)d_in[8];
    const float* ln_b   = (const float*)d_in[9];
    const float* ff_w1  = (const float*)d_in[10];
    const float* ff_b1  = (const float*)d_in[11];
    const float* ff_w2  = (const float*)d_in[12];
    const float* ff_b2  = (const float*)d_in[13];
    const float* out_g  = (const float*)d_in[14];
    const float* out_b  = (const float*)d_in[15];
    float* out = (float*)d_out;

    float *res, *res2;
    __half *lnb, *qkv, *kv, *ctx, *ff, *wsa, *wca, *w1, *w2, *mem;
    cudaGetSymbolAddress((void**)&res,  g_res);
    cudaGetSymbolAddress((void**)&res2, g_res2);
    cudaGetSymbolAddress((void**)&lnb,  g_lnb);
    cudaGetSymbolAddress((void**)&qkv,  g_qkv);
    cudaGetSymbolAddress((void**)&kv,   g_kv);
    cudaGetSymbolAddress((void**)&ctx,  g_ctx);
    cudaGetSymbolAddress((void**)&ff,   g_ff);
    cudaGetSymbolAddress((void**)&wsa,  g_wsa);
    cudaGetSymbolAddress((void**)&wca,  g_wca);
    cudaGetSymbolAddress((void**)&w1,   g_w1);
    cudaGetSymbolAddress((void**)&w2,   g_w2);
    cudaGetSymbolAddress((void**)&mem,  g_mem);

    cudaFuncSetAttribute(attn_h<true>,  cudaFuncAttributeMaxDynamicSharedMemorySize, ATTN_SMEM);
    cudaFuncSetAttribute(attn_h<false>, cudaFuncAttributeMaxDynamicSharedMemorySize, ATTN_SMEM);
    cudaFuncSetAttribute((gemm_h<128,true,false,false,true >), cudaFuncAttributeMaxDynamicSharedMemorySize, GEMM_SMEM_128);
    cudaFuncSetAttribute((gemm_h<128,true,false,true ,true >), cudaFuncAttributeMaxDynamicSharedMemorySize, GEMM_SMEM_128);
    cudaFuncSetAttribute((gemm_h<64 ,true,true ,false,false>), cudaFuncAttributeMaxDynamicSharedMemorySize, GEMM_SMEM_64);
    cudaFuncSetAttribute((gemm_h<64 ,true,false,false,true >), cudaFuncAttributeMaxDynamicSharedMemorySize, GEMM_SMEM_64);

    embed_kernel<<<BT_, 256>>>(tgt, emb, res);
    {
        const size_t NW = (size_t)NL*4*DMODEL*DMODEL/4;
        const size_t NF = (size_t)NL*DFF_*DMODEL/4;
        const size_t NM = (size_t)BS_*DMODEL/4;
        const size_t total = 2*NW + 2*NF + NM;
        conv_all_kernel<<<(unsigned)((total + 255)/256), 256>>>(
            (const float4*)sa_w, (const float4*)ca_w,
            (const float4*)ff_w1, (const float4*)ff_w2, (const float4*)memory,
            wsa, wca, w1, w2, mem);
    }

    const dim3 g2304 (3*DMODEL/128, BT_/128);   // BN=128
    const dim3 g1536 (2*DMODEL/128, BS_/128);   // BN=128
    const dim3 g3072 (DFF_/128, BT_/128);       // BN=128
    const dim3 g768t (DMODEL/64, BT_/128);      // BN=64 -> 384 CTAs
    const dim3 attn_grid(TLEN_/128, NH, BB);
    const int  LN_GRID = BT_/8;                 // warp-per-row LN

    for (int i = 0; i < NL; i++) {
        const __half* saw = wsa + (size_t)i*4*DMODEL*DMODEL;
        const float*  sab = sa_b + (size_t)i*4*DMODEL;
        const __half* caw = wca + (size_t)i*4*DMODEL*DMODEL;
        const float*  cab = ca_b + (size_t)i*4*DMODEL;
        const float*  lg  = ln_g + (size_t)i*3*DMODEL;
        const float*  lb  = ln_b + (size_t)i*3*DMODEL;

        // ----- self attention -----
        ln_kernel<true><<<LN_GRID, 256>>>(res, lg, lb, lnb);
        gemm_h<128,true,false,false,true><<<g2304, 256, GEMM_SMEM_128>>>(lnb, saw, sab, nullptr, qkv,
                                                  BT_, 3*DMODEL, DMODEL);
        attn_h<true><<<attn_grid, 256, ATTN_SMEM>>>(
            qkv, 3*DMODEL, qkv + DMODEL, 3*DMODEL, qkv + 2*DMODEL, 3*DMODEL,
            tgt, TLEN_, ctx, DMODEL);
        gemm_h<64,true,true,false,false><<<g768t, 256, GEMM_SMEM_64>>>(ctx, saw + (size_t)3*DMODEL*DMODEL,
                                                sab + 3*DMODEL, res, res2,
                                                BT_, DMODEL, DMODEL);

        // ----- cross attention -----
        ln_kernel<true><<<LN_GRID, 256>>>(res2, lg + DMODEL, lb + DMODEL, lnb);
        gemm_h<64,true,false,false,true><<<g768t, 256, GEMM_SMEM_64>>>(lnb, caw, cab, nullptr, qkv,
                                                 BT_, DMODEL, DMODEL);
        gemm_h<128,true,false,false,true><<<g1536, 256, GEMM_SMEM_128>>>(mem, caw + (size_t)DMODEL*DMODEL,
                                                  cab + DMODEL, nullptr, kv,
                                                  BS_, 2*DMODEL, DMODEL);
        attn_h<false><<<attn_grid, 256, ATTN_SMEM>>>(
            qkv, DMODEL, kv, 2*DMODEL, kv + DMODEL, 2*DMODEL,
            src, SLEN_, ctx, DMODEL);
        gemm_h<64,true,true,false,false><<<g768t, 256, GEMM_SMEM_64>>>(ctx, caw + (size_t)3*DMODEL*DMODEL,
                                                cab + 3*DMODEL, res2, res,
                                                BT_, DMODEL, DMODEL);

        // ----- FFN -----
        ln_kernel<true><<<LN_GRID, 256>>>(res, lg + 2*DMODEL, lb + 2*DMODEL, lnb);
        gemm_h<128,true,false,true,true><<<g3072, 256, GEMM_SMEM_128>>>(lnb, w1 + (size_t)i*DFF_*DMODEL,
                                                 ff_b1 + (size_t)i*DFF_, nullptr, ff,
                                                 BT_, DFF_, DMODEL);
        gemm_h<64,true,true,false,false><<<g768t, 256, GEMM_SMEM_64>>>(ff, w2 + (size_t)i*DMODEL*DFF_,
                                                ff_b2 + (size_t)i*DMODEL, res, res2,
                                                BT_, DMODEL, DFF_);

        float* tmp = res; res = res2; res2 = tmp;
    }

    ln_kernel<false><<<LN_GRID, 256>>>(res, out_g, out_b, out);
}